// round 16
// baseline (speedup 1.0000x reference)
#include <cuda_runtime.h>
#include <cuda_bf16.h>

#define BB   2
#define SS   256
#define INP  80
#define HH   128
#define GG   512
#define FF   256
#define NCC  40
#define WW   64
#define HID  100

typedef unsigned long long u64;

__device__ float g_wihT [4][FF*GG];
__device__ u64   g_wsP  [3][128*128];
__device__ __align__(16) u64 g_wsPc[128*128];   // w_s1 c-part, [h][k2] contiguous
__device__ float g_preF [SS*BB*GG];
__device__ float g_preB [SS*BB*GG];
__device__ float g_h0   [BB*SS*FF];
__device__ float g_rnn  [BB*SS*FF];
__device__ float g_cum  [BB*SS*FF];
__device__ float g_Pd   [BB*SS*HID];
__device__ float g_Pe   [BB*SS*HID];
__device__ float g_sband[BB*SS*WW];

__device__ __forceinline__ void fma2(u64 &d, u64 a, u64 b) {
    asm("fma.rn.f32x2 %0, %1, %2, %0;" : "+l"(d) : "l"(a), "l"(b));
}
__device__ __forceinline__ float2 u2f(u64 v) {
    float2 f; asm("mov.b64 {%0,%1}, %2;" : "=f"(f.x), "=f"(f.y) : "l"(v)); return f;
}
__device__ __forceinline__ u64 f2u(float x, float y) {
    u64 v; asm("mov.b64 %0, {%1,%2};" : "=l"(v) : "f"(x), "f"(y)); return v;
}
__device__ __forceinline__ unsigned smem_u32(const void* p) {
    unsigned a;
    asm("{ .reg .u64 t; cvta.to.shared.u64 t, %1; cvt.u32.u64 %0, t; }" : "=r"(a) : "l"(p));
    return a;
}
__device__ __forceinline__ float tanha(float x) {
    float r; asm("tanh.approx.f32 %0, %1;" : "=f"(r) : "f"(x)); return r;
}
__device__ __forceinline__ unsigned orderable(float v) {
    unsigned u = __float_as_uint(v);
    return (u & 0x80000000u) ? ~u : (u | 0x80000000u);
}
__device__ __forceinline__ float unorder(unsigned u) {
    return (u & 0x80000000u) ? __uint_as_float(u & 0x7FFFFFFFu)
                             : __uint_as_float(~u);
}
__device__ __forceinline__ void mbar_init(unsigned mb, unsigned cnt) {
    asm volatile("mbarrier.init.shared.b64 [%0], %1;" :: "r"(mb), "r"(cnt) : "memory");
}
__device__ __forceinline__ void mbar_expect(unsigned mb, unsigned bytes) {
    asm volatile("mbarrier.arrive.expect_tx.shared.b64 _, [%0], %1;"
                 :: "r"(mb), "r"(bytes) : "memory");
}
__device__ __forceinline__ void mbar_wait_par(unsigned mb, unsigned par) {
    unsigned done = 0;
    do {
        asm volatile("{\n\t.reg .pred p;\n\t"
            "mbarrier.try_wait.parity.acquire.cta.shared::cta.b64 p, [%1], %2, 0x989680;\n\t"
            "selp.b32 %0,1,0,p;\n\t}" : "=r"(done) : "r"(mb), "r"(par) : "memory");
    } while (!done);
}
__device__ __forceinline__ void bulk_copy_peer(unsigned dst, unsigned src, unsigned mbar_remote) {
    asm volatile("cp.async.bulk.shared::cluster.shared::cta.mbarrier::complete_tx::bytes "
                 "[%0], [%1], 128, [%2];"
                 :: "r"(dst), "r"(src), "r"(mbar_remote) : "memory");
}
__device__ __forceinline__ void fence_async() {
    asm volatile("fence.proxy.async.shared::cta;" ::: "memory");
}

// ---------------- prep: transpose + ws1 pack, one kernel ----------------
__global__ void k_prep(const float* __restrict__ w0, const float* __restrict__ w1,
                       const float* __restrict__ w2, const float* __restrict__ w3,
                       const float* __restrict__ ws1, float* __restrict__ wT) {
    int m = blockIdx.y, c = blockIdx.x, tt = threadIdx.x;
    if (m < 4) {
        const float* w = (m == 0) ? w0 : (m == 1) ? w1 : (m == 2) ? w2 : w3;
        int cols = (m < 2) ? INP : FF;
        if (c < cols) wT[m*FF*GG + c*GG + tt] = w[tt*cols + c];
    } else {
        if (c < 128) {
            int p = tt >> 7, h = tt & 127;
            if (p < 3) {
                u64 v = 0ull;
                if (h < HID) v = f2u(ws1[h*768 + p*256 + 2*c], ws1[h*768 + p*256 + 2*c + 1]);
                g_wsP[p][c*128 + h] = v;
                if (p == 0) g_wsPc[h*128 + c] = v;
            }
        }
    }
}

// ---------------- pre = x @ Wih^T + b: 16 steps/block, g split in halves ----------------
// grid (SS/16, BB, 4): z = dir*2 + ghalf.  blockDim 256.
__global__ void k_pre16s(const float* __restrict__ xin, const float* __restrict__ wTbase,
                         const float* __restrict__ bF, const float* __restrict__ bB,
                         float* __restrict__ preFo, float* __restrict__ preBo, int Din) {
    __shared__ float xs[16][FF];
    int z  = blockIdx.z >> 1;       // dir
    int gh = blockIdx.z & 1;        // g half
    const float* wT   = wTbase + z*FF*GG;
    const float* bias = z ? bB : bF;
    float* pre        = z ? preBo : preFo;
    int sb = blockIdx.x * 16, b = blockIdx.y;
    int tid = threadIdx.x;          // 256
    int g = gh*256 + tid;
    for (int idx = tid; idx < 16*Din; idx += 256) {
        int j = idx / Din, k = idx - j*Din;
        xs[j][k] = xin[(b*SS + sb + j)*Din + k];
    }
    __syncthreads();
    float bi = bias[g];
    float acc[16];
    #pragma unroll
    for (int j = 0; j < 16; j++) acc[j] = bi;
    for (int i = 0; i < Din; i += 2) {
        float w0 = wT[(i    )*GG + g];
        float w1 = wT[(i + 1)*GG + g];
        #pragma unroll
        for (int j = 0; j < 16; j++)
            acc[j] += xs[j][i]*w0 + xs[j][i+1]*w1;
    }
    #pragma unroll
    for (int j = 0; j < 16; j++) pre[((sb + j)*BB + b)*GG + g] = acc[j];
}

// ---------------- LSTM scan: 8-CTA cluster per dir, one-hop bulk exchange ----------------
__global__ void __launch_bounds__(128, 1) __cluster_dims__(8, 1, 1)
k_scan8(const float* __restrict__ preFp, const float* __restrict__ preBp,
        const float* __restrict__ whFp, const float* __restrict__ whBp,
        float* __restrict__ hout) {
    int dir  = blockIdx.x >> 3;
    int r    = blockIdx.x & 7;
    int q    = r & 3;
    int bt   = r >> 2;
    const float* pre = dir ? preBp : preFp;
    const u64*   W   = (const u64*)(dir ? whBp : whFp);   // [512 rows][64 u64]
    int t  = threadIdx.x;          // 128
    int g  = t >> 5;
    int hl = t & 31;
    int row = g*HH + q*32 + hl;

    __shared__ __align__(16) float hsf[2][HH];     // [buf][k] for this batch
    __shared__ float gs[4][32];                    // [gate][local unit]
    __shared__ __align__(8) u64 mbar[2];           // one barrier per buffer

    u64 w[64];
    #pragma unroll
    for (int c = 0; c < 4; c++) {
        int qb = 16 * ((q + c) & 3);
        #pragma unroll
        for (int j = 0; j < 16; j++) w[c*16 + j] = W[row*64 + qb + j];
    }

    for (int i = t; i < 2*HH; i += 128) ((float*)hsf)[i] = 0.f;
    unsigned mb = smem_u32(&mbar[0]);
    if (t == 0) { mbar_init(mb, 1); mbar_init(mb + 8, 1); }
    __syncthreads();
    if (t == 0) { mbar_expect(mb, 384); mbar_expect(mb + 8, 384); }
    asm volatile("barrier.cluster.arrive.aligned;" ::: "memory");
    asm volatile("barrier.cluster.wait.aligned;"   ::: "memory");

    unsigned lbase = smem_u32(&hsf[0][0]);
    unsigned rbp[3], rmb[3];
    #pragma unroll
    for (int pi = 0; pi < 3; pi++) {
        int pr = (bt << 2) | ((q + 1 + pi) & 3);   // same-batch peer
        asm("mapa.shared::cluster.u32 %0, %1, %2;" : "=r"(rmb[pi]) : "r"(mb),    "r"(pr));
        asm("mapa.shared::cluster.u32 %0, %1, %2;" : "=r"(rbp[pi]) : "r"(lbase), "r"(pr));
    }

    int eh = t & 31;               // epilogue lane (t < 32)
    float cst = 0.f;
    int s0 = dir ? (SS - 1) : 0;
    float pcur = __ldg(&pre[(s0*BB + bt)*GG + row]);
    unsigned ph0 = 0, ph1 = 0;

    for (int s_ = 0; s_ < SS; s_++) {
        int s  = dir ? (SS - 1 - s_) : s_;
        int sn = dir ? (s - 1 < 0 ? 0 : s - 1) : (s + 1 > SS - 1 ? SS - 1 : s + 1);
        float pnext = __ldg(&pre[(sn*BB + bt)*GG + row]);
        int rb = (s_ + 1) & 1;
        int wb = s_ & 1;
        const u64* h2 = (const u64*)hsf[rb];
        u64 a0 = 0ull, a1 = 0ull, a2 = 0ull, a3 = 0ull;
        {   // local quarter — ordered by __syncthreads
            const u64* hq = h2 + 16*q;
            #pragma unroll
            for (int j = 0; j < 16; j += 2) {
                ulonglong2 x = *(const ulonglong2*)(hq + j);
                fma2(a0, w[j], x.x);  fma2(a1, w[j + 1], x.y);
            }
        }
        if (s_ > 0) {                              // wait peers' h(s_-1) in buffer rb
            unsigned bmb = mb + 8u*(unsigned)rb;
            mbar_wait_par(bmb, rb ? ph1 : ph0);
            if (t == 0) mbar_expect(bmb, 384);     // re-arm for next use (s_+2)
            if (rb) ph1 ^= 1; else ph0 ^= 1;
        }
        #pragma unroll
        for (int c = 1; c < 4; c++) {
            const u64* hq = h2 + 16*((q + c) & 3);
            #pragma unroll
            for (int j = 0; j < 16; j += 4) {
                ulonglong2 x0 = *(const ulonglong2*)(hq + j);
                ulonglong2 x1 = *(const ulonglong2*)(hq + j + 2);
                fma2(a0, w[c*16 + j],     x0.x);  fma2(a1, w[c*16 + j + 1], x0.y);
                fma2(a2, w[c*16 + j + 2], x1.x);  fma2(a3, w[c*16 + j + 3], x1.y);
            }
        }
        float2 fa = u2f(a0), fb = u2f(a1), fc = u2f(a2), fd = u2f(a3);
        gs[g][hl] = ((fa.x + fa.y) + (fb.x + fb.y)) + ((fc.x + fc.y) + (fd.x + fd.y)) + pcur;
        pcur = pnext;
        __syncthreads();                           // gates ready; reads of rb done
        if (t < 32) {
            float ig = 0.5f*tanha(0.5f*gs[0][eh]) + 0.5f;
            float fg = 0.5f*tanha(0.5f*gs[1][eh]) + 0.5f;
            float gg = tanha(gs[2][eh]);
            float og = 0.5f*tanha(0.5f*gs[3][eh]) + 0.5f;
            cst = fg*cst + ig*gg;
            float hv = og * tanha(cst);
            hsf[wb][q*32 + eh] = hv;
            __syncwarp();
            if (eh < 3) {                          // ship quarter to 3 peers, one hop each
                fence_async();
                unsigned off = (unsigned)((wb*HH + q*32) * 4);
                bulk_copy_peer(rbp[eh] + off, lbase + off, rmb[eh] + 8u*(unsigned)wb);
            }
            hout[(bt*SS + s)*FF + dir*HH + q*32 + eh] = hv;
        }
        __syncthreads();                           // local quarter of wb visible to CTA
    }
    asm volatile("barrier.cluster.arrive.aligned;" ::: "memory");
    asm volatile("barrier.cluster.wait.aligned;"   ::: "memory");
}

// ---------------- cls / bin MLPs, 4 timesteps per block ----------------
__global__ void k_clsbin4(const float* __restrict__ rnn,
    const float* ac0, const float* __restrict__ wc1, const float* __restrict__ bc1,
    const float* ac1, const float* __restrict__ wc2, const float* __restrict__ bc2,
    const float* ab0, const float* __restrict__ wb1, const float* __restrict__ bb1,
    const float* ab1, const float* __restrict__ wb2, const float* __restrict__ bb2,
    float* __restrict__ out) {
    int sb = blockIdx.x * 4, b = blockIdx.y, t = threadIdx.x; // blockDim = 192
    __shared__ float xc[4][FF], xb[4][FF], hc[4][80], hb[4][80];
    float a0c = *ac0, a0b = *ab0;
    for (int k = t; k < 4*FF; k += 192) {
        int j = k >> 8, kk = k & 255;
        float v = rnn[(b*SS + sb + j)*FF + kk];
        xc[j][kk] = v >= 0.f ? v : a0c*v;
        xb[j][kk] = v >= 0.f ? v : a0b*v;
    }
    __syncthreads();
    if (t < 80) {
        float acc[4];
        float bv = bc1[t];
        #pragma unroll
        for (int j = 0; j < 4; j++) acc[j] = bv;
        const float* w = wc1 + t*FF;
        #pragma unroll 4
        for (int k = 0; k < FF; k++) {
            float wv = w[k];
            #pragma unroll
            for (int j = 0; j < 4; j++) acc[j] += xc[j][k]*wv;
        }
        float a1 = *ac1;
        #pragma unroll
        for (int j = 0; j < 4; j++) hc[j][t] = acc[j] >= 0.f ? acc[j] : a1*acc[j];
    } else if (t < 160) {
        int g = t - 80;
        float acc[4];
        float bv = bb1[g];
        #pragma unroll
        for (int j = 0; j < 4; j++) acc[j] = bv;
        const float* w = wb1 + g*FF;
        #pragma unroll 4
        for (int k = 0; k < FF; k++) {
            float wv = w[k];
            #pragma unroll
            for (int j = 0; j < 4; j++) acc[j] += xb[j][k]*wv;
        }
        float a1 = *ab1;
        #pragma unroll
        for (int j = 0; j < 4; j++) hb[j][g] = acc[j] >= 0.f ? acc[j] : a1*acc[j];
    }
    __syncthreads();
    if (t < NCC) {
        float acc[4];
        float bv = bc2[t];
        #pragma unroll
        for (int j = 0; j < 4; j++) acc[j] = bv;
        const float* w = wc2 + t*80;
        #pragma unroll 4
        for (int k = 0; k < 80; k++) {
            float wv = w[k];
            #pragma unroll
            for (int j = 0; j < 4; j++) acc[j] += hc[j][k]*wv;
        }
        #pragma unroll
        for (int j = 0; j < 4; j++) out[(b*SS + sb + j)*NCC + t] = acc[j];
    } else if (t < NCC + 2) {
        int o = t - NCC;
        float acc[4];
        float bv = bb2[o];
        #pragma unroll
        for (int j = 0; j < 4; j++) acc[j] = bv;
        const float* w = wb2 + o*80;
        #pragma unroll 4
        for (int k = 0; k < 80; k++) {
            float wv = w[k];
            #pragma unroll
            for (int j = 0; j < 4; j++) acc[j] += hb[j][k]*wv;
        }
        #pragma unroll
        for (int j = 0; j < 4; j++) out[20480 + (b*SS + sb + j)*2 + o] = acc[j];
    }
}

// ---------------- cumsum (software-pipelined loads) ----------------
__global__ void k_cum(const float* __restrict__ rnn) {
    int b = blockIdx.x, k = threadIdx.x;
    float run = 0.f;
    float v[8], vn[8];
    #pragma unroll
    for (int j = 0; j < 8; j++) v[j] = rnn[(b*SS + j)*FF + k];
    for (int t0 = 0; t0 < SS; t0 += 8) {
        if (t0 + 8 < SS) {
            #pragma unroll
            for (int j = 0; j < 8; j++) vn[j] = rnn[(b*SS + t0 + 8 + j)*FF + k];
        }
        #pragma unroll
        for (int j = 0; j < 8; j++) { run += v[j]; g_cum[(b*SS + t0 + j)*FF + k] = run; }
        #pragma unroll
        for (int j = 0; j < 8; j++) v[j] = vn[j];
    }
}

// ---------------- Pd / Pe, 2 timesteps per block ----------------
__global__ void k_pdpe2(const float* __restrict__ rnn, const float* as0, const float* __restrict__ bs1) {
    int sp = blockIdx.x * 2, b = blockIdx.y, t = threadIdx.x; // blockDim = 128
    __shared__ __align__(16) float xr[2][FF];
    float a0 = *as0;
    #pragma unroll
    for (int ss = 0; ss < 2; ss++) {
        float v0 = rnn[(b*SS + sp + ss)*FF + 2*t];
        float v1 = rnn[(b*SS + sp + ss)*FF + 2*t + 1];
        xr[ss][2*t]     = v0 >= 0.f ? v0 : a0*v0;
        xr[ss][2*t + 1] = v1 >= 0.f ? v1 : a0*v1;
    }
    __syncthreads();
    if (t < HID) {
        u64 d0 = 0ull, e0 = 0ull, d1 = 0ull, e1 = 0ull;
        const u64* xp0 = (const u64*)xr[0];
        const u64* xp1 = (const u64*)xr[1];
        #pragma unroll 4
        for (int k2 = 0; k2 < 128; k2++) {
            u64 wd = g_wsP[1][k2*128 + t];
            u64 we = g_wsP[2][k2*128 + t];
            u64 x0 = xp0[k2], x1 = xp1[k2];
            fma2(d0, wd, x0);  fma2(e0, we, x0);
            fma2(d1, wd, x1);  fma2(e1, we, x1);
        }
        float bsv = bs1[t];
        float2 f;
        f = u2f(d0); g_Pd[(b*SS + sp    )*HID + t] = f.x + f.y;
        f = u2f(e0); g_Pe[(b*SS + sp    )*HID + t] = f.x + f.y + bsv;
        f = u2f(d1); g_Pd[(b*SS + sp + 1)*HID + t] = f.x + f.y;
        f = u2f(e1); g_Pe[(b*SS + sp + 1)*HID + t] = f.x + f.y + bsv;
    }
}

// ---------------- banded score MLP, register-blocked 16 windows, vectorized ----------------
__global__ void k_scores(const float* as0, const float* as1,
                         const float* __restrict__ ws2, const float* bs2) {
    int i = blockIdx.x, b = blockIdx.y, t = threadIdx.x; // blockDim = 128
    if (i == 0) return;
    __shared__ __align__(16) float cdf[16][FF];
    __shared__ float sv[16][104];
    const ulonglong2 (*cd2)[64] = (const ulonglong2 (*)[64])cdf;
    float a0 = *as0, a1 = *as1, b2 = *bs2;
    u64 civ = ((const u64*)(g_cum + (b*SS + i)*FF))[t];
    float2 ci = u2f(civ);
    float pei = (t < HID) ? g_Pe[(b*SS + i)*HID + t] : 0.f;
    float w2  = (t < HID) ? ws2[t] : 0.f;
    int wid = t >> 5, lane = t & 31;

    for (int gq = 0; gq < 4; gq++) {
        #pragma unroll 4
        for (int p = 0; p < 16; p++) {
            int j = i - WW + gq*16 + p;
            float c0 = 0.f, c1 = 0.f;
            if (j >= 0) {
                float2 cj = u2f(((const u64*)(g_cum + (b*SS + j)*FF))[t]);
                c0 = ci.x - cj.x;  c1 = ci.y - cj.y;
                c0 = c0 >= 0.f ? c0 : a0*c0;
                c1 = c1 >= 0.f ? c1 : a0*c1;
            }
            ((u64*)cdf[p])[t] = f2u(c0, c1);
        }
        __syncthreads();
        if (t < HID) {
            u64 acc[16];
            #pragma unroll
            for (int p = 0; p < 16; p++) acc[p] = 0ull;
            const ulonglong2* wr = (const ulonglong2*)(g_wsPc + (size_t)t*128);
            #pragma unroll 2
            for (int k4 = 0; k4 < 64; k4++) {
                ulonglong2 wv = __ldg(&wr[k4]);
                #pragma unroll
                for (int p = 0; p < 16; p++) {
                    ulonglong2 x = cd2[p][k4];
                    fma2(acc[p], wv.x, x.x);
                    fma2(acc[p], wv.y, x.y);
                }
            }
            #pragma unroll
            for (int p = 0; p < 16; p++) {
                int j = i - WW + gq*16 + p;
                float2 f = u2f(acc[p]);
                float pd = (j >= 0) ? g_Pd[(b*SS + j)*HID + t] : 0.f;
                float hid = f.x + f.y + pd + pei;
                float ph  = hid >= 0.f ? hid : a1*hid;
                sv[p][t] = ph * w2;
            }
        }
        __syncthreads();
        #pragma unroll
        for (int qq = 0; qq < 4; qq++) {
            int p = wid + qq*4;
            float v = sv[p][lane] + sv[p][lane + 32] + sv[p][lane + 64]
                    + (lane < 4 ? sv[p][lane + 96] : 0.f);
            for (int off = 16; off; off >>= 1) v += __shfl_down_sync(0xffffffffu, v, off);
            if (lane == 0) {
                int w = gq*16 + p;
                int j = i - WW + w;
                g_sband[(b*SS + i)*WW + w] = (j >= 0) ? v + b2 : -1000000000.0f;
            }
        }
        __syncthreads();
    }
}

// ---------------- DP + backtrack (sband preloaded to smem, redux argmax) ----------------
__global__ void k_dp(const int* __restrict__ lengths, float* __restrict__ out) {
    extern __shared__ __align__(16) float sbf[];   // 2*256*64 floats = 128 KB
    __shared__ float best[BB][SS];
    __shared__ int   bp[BB][SS];
    int t = threadIdx.x;          // blockDim = 256
    {
        float4* dst = (float4*)sbf;
        const float4* src = (const float4*)g_sband;
        #pragma unroll 4
        for (int idx = t; idx < BB*SS*WW/4; idx += 256) dst[idx] = __ldg(src + idx);
    }
    for (int idx = t; idx < BB*SS; idx += 256) { out[21504 + idx] = 0.f; best[idx >> 8][idx & 255] = 0.f; }
    if (t < BB) bp[t][0] = 0;
    __syncthreads();
    if (t < 64) {
        int b = t >> 5, lane = t & 31;
        for (int i = 1; i < SS; i++) {
            int w1 = lane, w2 = lane + 32;
            int j1 = i - WW + w1, j2 = i - WW + w2;
            const float* sr = sbf + (b*SS + i)*WW;
            float c1 = (j1 >= 0) ? best[b][j1] + sr[w1] : -1000000000.0f;
            float c2 = (j2 >= 0) ? best[b][j2] + sr[w2] : -1000000000.0f;
            float v; int jj;
            if (c2 > c1) { v = c2; jj = j2; } else { v = c1; jj = j1; }   // tie -> smaller j
            unsigned key = orderable(v), kmax;
            asm("redux.sync.max.u32 %0, %1, 0xffffffff;" : "=r"(kmax) : "r"(key));
            unsigned jc = (key == kmax) ? (unsigned)jj : 0xFFFFFFFFu;
            unsigned jmin;
            asm("redux.sync.min.u32 %0, %1, 0xffffffff;" : "=r"(jmin) : "r"(jc));
            if (lane == 0) { best[b][i] = unorder(kmax); bp[b][i] = (int)jmin; }
            __syncwarp();
        }
    }
    __syncthreads();
    if (t < BB) {
        int cur = lengths[t] - 1;
        if (cur < 0) cur = 0;
        float acc = 0.f;
        while (true) {
            out[21504 + t*SS + cur] = 1.f;
            if (cur == 0) break;
            int prev = bp[t][cur];
            acc += sbf[(t*SS + cur)*WW + (prev - (cur - WW))];
            cur = prev;
        }
        out[22016 + t] = acc;
    }
}

// ---------------- launch ----------------
extern "C" void kernel_launch(void* const* d_in, const int* in_sizes, int n_in,
                              void* d_out, int out_size) {
    (void)in_sizes; (void)n_in; (void)out_size;
    const float* x        = (const float*)d_in[0];
    const int*   lengths  = (const int*)  d_in[1];
    const float* wih[4]   = {(const float*)d_in[2], (const float*)d_in[5],
                             (const float*)d_in[8], (const float*)d_in[11]};
    const float* whh[4]   = {(const float*)d_in[3], (const float*)d_in[6],
                             (const float*)d_in[9], (const float*)d_in[12]};
    const float* bl[4]    = {(const float*)d_in[4], (const float*)d_in[7],
                             (const float*)d_in[10], (const float*)d_in[13]};
    const float* a_s0 = (const float*)d_in[14];
    const float* w_s1 = (const float*)d_in[15];
    const float* b_s1 = (const float*)d_in[16];
    const float* a_s1 = (const float*)d_in[17];
    const float* w_s2 = (const float*)d_in[18];
    const float* b_s2 = (const float*)d_in[19];
    const float* a_c0 = (const float*)d_in[20];
    const float* w_c1 = (const float*)d_in[21];
    const float* b_c1 = (const float*)d_in[22];
    const float* a_c1 = (const float*)d_in[23];
    const float* w_c2 = (const float*)d_in[24];
    const float* b_c2 = (const float*)d_in[25];
    const float* a_b0 = (const float*)d_in[26];
    const float* w_b1 = (const float*)d_in[27];
    const float* b_b1 = (const float*)d_in[28];
    const float* a_b1 = (const float*)d_in[29];
    const float* w_b2 = (const float*)d_in[30];
    const float* b_b2 = (const float*)d_in[31];
    float* out = (float*)d_out;

    float *wihT, *preF, *preB, *h0, *rnn;
    cudaGetSymbolAddress((void**)&wihT, g_wihT);
    cudaGetSymbolAddress((void**)&preF, g_preF);
    cudaGetSymbolAddress((void**)&preB, g_preB);
    cudaGetSymbolAddress((void**)&h0,   g_h0);
    cudaGetSymbolAddress((void**)&rnn,  g_rnn);

    static int dp_attr_set = 0;
    if (!dp_attr_set) {
        cudaFuncSetAttribute(k_dp, cudaFuncAttributeMaxDynamicSharedMemorySize, BB*SS*WW*4);
        dp_attr_set = 1;
    }

    k_prep<<<dim3(FF, 5), GG>>>(wih[0], wih[1], wih[2], wih[3], w_s1, wihT);

    dim3 gpre(SS/16, BB, 4);
    // layer 0
    k_pre16s<<<gpre, 256>>>(x, wihT, bl[0], bl[1], preF, preB, INP);
    k_scan8<<<16, 128>>>(preF, preB, whh[0], whh[1], h0);
    // layer 1
    k_pre16s<<<gpre, 256>>>(h0, wihT + 2*FF*GG, bl[2], bl[3], preF, preB, FF);
    k_scan8<<<16, 128>>>(preF, preB, whh[2], whh[3], rnn);

    k_clsbin4<<<dim3(SS/4, BB), 192>>>(rnn, a_c0, w_c1, b_c1, a_c1, w_c2, b_c2,
                                            a_b0, w_b1, b_b1, a_b1, w_b2, b_b2, out);
    k_cum<<<BB, FF>>>(rnn);
    k_pdpe2<<<dim3(SS/2, BB), 128>>>(rnn, a_s0, b_s1);
    k_scores<<<dim3(SS, BB), 128>>>(a_s0, a_s1, w_s2, b_s2);
    k_dp<<<1, 256, BB*SS*WW*4>>>(lengths, out);
}